// round 7
// baseline (speedup 1.0000x reference)
#include <cuda_runtime.h>
#include <cstdint>

// Problem constants (from reference)
#define NTOKENS    8192
#define TOPK       2
#define HIDDEN     4096
#define NUM_GROUPS 2
#define M_FULL     (NTOKENS * TOPK)   // 16384
#define NIDX       (NTOKENS * TOPK)   // 16384 index elements

// Device flag: 1 if scatter_index is int64, 0 if int32 (detected at runtime).
__device__ int g_is64;

// ---------------------------------------------------------------------------
// Dtype detection (single block). View the first 16384 int32 words — safe for
// both int32 (64KB buffer, all words) and int64 (128KB, first half).
// If int64: odd words are high halves of values < 16384 -> all zero.
// If int32: odd words are random indices -> OR is nonzero w.p. ~1.
// ---------------------------------------------------------------------------
__global__ void k_detect(const int* __restrict__ idx32) {
    __shared__ int s_or[32];
    int v = 0;
    // 1024 threads, 8 odd-words each: covers odd indices 1,3,...,16383
    #pragma unroll
    for (int r = 0; r < 8; r++) {
        int w = threadIdx.x + r * 1024;          // 0..8191
        v |= idx32[2 * w + 1];
    }
    #pragma unroll
    for (int off = 16; off > 0; off >>= 1)
        v |= __shfl_down_sync(0xFFFFFFFFu, v, off);
    if ((threadIdx.x & 31) == 0) s_or[threadIdx.x >> 5] = v;
    __syncthreads();
    if (threadIdx.x < 32) {
        int t = s_or[threadIdx.x];
        #pragma unroll
        for (int off = 16; off > 0; off >>= 1)
            t |= __shfl_down_sync(0xFFFFFFFFu, t, off);
        if (threadIdx.x == 0) g_is64 = (t == 0) ? 1 : 0;
    }
}

// ---------------------------------------------------------------------------
// Main kernel: out[t, :] = buf[0,i0,:] + buf[0,i1,:] + buf[1,i0,:] + buf[1,i1,:]
//   One 256-thread CTA per token. Each thread: 4 float4 chunks, each chunk
//   summing 4 source rows -> 16 LDG.128 + 4 STG.128 per thread, coalesced.
// ---------------------------------------------------------------------------
__global__ __launch_bounds__(256) void k_gather_sum(
    const float* __restrict__ buf,
    const void*  __restrict__ idx,
    float*       __restrict__ out)
{
    const int t = blockIdx.x;

    int i0, i1;
    if (g_is64) {
        const long long* p = (const long long*)idx;
        i0 = (int)p[(size_t)t * TOPK + 0];
        i1 = (int)p[(size_t)t * TOPK + 1];
    } else {
        const int* p = (const int*)idx;
        i0 = p[t * TOPK + 0];
        i1 = p[t * TOPK + 1];
    }

    const float4* __restrict__ b4 = (const float4*)buf;
    const size_t R = HIDDEN / 4;                     // 1024 float4 per row
    const size_t p00 = (size_t)i0 * R;               // group 0, i0
    const size_t p01 = (size_t)i1 * R;               // group 0, i1
    const size_t p10 = ((size_t)M_FULL + i0) * R;    // group 1, i0
    const size_t p11 = ((size_t)M_FULL + i1) * R;    // group 1, i1

    float4* __restrict__ o4 = (float4*)out + (size_t)t * R;

    #pragma unroll
    for (int c = 0; c < 4; c++) {
        const int jj = threadIdx.x + c * 256;
        float4 a = b4[p00 + jj];
        float4 b = b4[p01 + jj];
        float4 d = b4[p10 + jj];
        float4 e = b4[p11 + jj];
        float4 s;
        s.x = (a.x + b.x) + (d.x + e.x);
        s.y = (a.y + b.y) + (d.y + e.y);
        s.z = (a.z + b.z) + (d.z + e.z);
        s.w = (a.w + b.w) + (d.w + e.w);
        o4[jj] = s;
    }
}

// ---------------------------------------------------------------------------
// Launch contract
//   d_in[0]: gemm_buffer   float32 [NUM_GROUPS, M_FULL, HIDDEN]
//   d_in[1]: scatter_index int32 or int64 [NTOKENS, TOPK] (device-detected)
//   d_out  : float32 [NTOKENS, HIDDEN]
// ---------------------------------------------------------------------------
extern "C" void kernel_launch(void* const* d_in, const int* in_sizes, int n_in,
                              void* d_out, int out_size) {
    const float* buf = (const float*)d_in[0];
    const void*  idx = d_in[1];
    float*       out = (float*)d_out;

    k_detect<<<1, 1024>>>((const int*)idx);
    k_gather_sum<<<NTOKENS, 256>>>(buf, idx, out);
}

// round 8
// speedup vs baseline: 1.0041x; 1.0041x over previous
#include <cuda_runtime.h>
#include <cstdint>

// Problem constants (from reference)
#define NTOKENS    8192
#define TOPK       2
#define HIDDEN     4096
#define NUM_GROUPS 2
#define M_FULL     (NTOKENS * TOPK)   // 16384
#define NIDX       (NTOKENS * TOPK)   // 16384 index elements

// Device flag: 1 if scatter_index is int64, 0 if int32 (detected at runtime).
__device__ int g_is64;

// ---------------------------------------------------------------------------
// Dtype detection (single block). View the first 16384 int32 words — safe for
// both int32 (64KB buffer, all words) and int64 (128KB, first half).
// If int64: odd words are high halves of values < 16384 -> all zero.
// If int32: odd words are random indices -> OR is nonzero w.p. ~1.
// ---------------------------------------------------------------------------
__global__ void k_detect(const int* __restrict__ idx32) {
    __shared__ int s_or[32];
    int v = 0;
    // 1024 threads, 8 odd-words each: covers odd indices 1,3,...,16383
    #pragma unroll
    for (int r = 0; r < 8; r++) {
        int w = threadIdx.x + r * 1024;          // 0..8191
        v |= idx32[2 * w + 1];
    }
    #pragma unroll
    for (int off = 16; off > 0; off >>= 1)
        v |= __shfl_down_sync(0xFFFFFFFFu, v, off);
    if ((threadIdx.x & 31) == 0) s_or[threadIdx.x >> 5] = v;
    __syncthreads();
    if (threadIdx.x < 32) {
        int t = s_or[threadIdx.x];
        #pragma unroll
        for (int off = 16; off > 0; off >>= 1)
            t |= __shfl_down_sync(0xFFFFFFFFu, t, off);
        if (threadIdx.x == 0) g_is64 = (t == 0) ? 1 : 0;
    }
}

// ---------------------------------------------------------------------------
// Main kernel: out[t, :] = buf[0,i0,:] + buf[0,i1,:] + buf[1,i0,:] + buf[1,i1,:]
//   One 256-thread CTA per token. Each thread: 4 float4 chunks, each chunk
//   summing 4 source rows -> 16 LDG.128 + 4 STG.128 per thread, coalesced.
// ---------------------------------------------------------------------------
__global__ __launch_bounds__(256) void k_gather_sum(
    const float* __restrict__ buf,
    const void*  __restrict__ idx,
    float*       __restrict__ out)
{
    const int t = blockIdx.x;

    int i0, i1;
    if (g_is64) {
        const long long* p = (const long long*)idx;
        i0 = (int)p[(size_t)t * TOPK + 0];
        i1 = (int)p[(size_t)t * TOPK + 1];
    } else {
        const int* p = (const int*)idx;
        i0 = p[t * TOPK + 0];
        i1 = p[t * TOPK + 1];
    }

    const float4* __restrict__ b4 = (const float4*)buf;
    const size_t R = HIDDEN / 4;                     // 1024 float4 per row
    const size_t p00 = (size_t)i0 * R;               // group 0, i0
    const size_t p01 = (size_t)i1 * R;               // group 0, i1
    const size_t p10 = ((size_t)M_FULL + i0) * R;    // group 1, i0
    const size_t p11 = ((size_t)M_FULL + i1) * R;    // group 1, i1

    float4* __restrict__ o4 = (float4*)out + (size_t)t * R;

    #pragma unroll
    for (int c = 0; c < 4; c++) {
        const int jj = threadIdx.x + c * 256;
        float4 a = b4[p00 + jj];
        float4 b = b4[p01 + jj];
        float4 d = b4[p10 + jj];
        float4 e = b4[p11 + jj];
        float4 s;
        s.x = (a.x + b.x) + (d.x + e.x);
        s.y = (a.y + b.y) + (d.y + e.y);
        s.z = (a.z + b.z) + (d.z + e.z);
        s.w = (a.w + b.w) + (d.w + e.w);
        o4[jj] = s;
    }
}

// ---------------------------------------------------------------------------
// Launch contract
//   d_in[0]: gemm_buffer   float32 [NUM_GROUPS, M_FULL, HIDDEN]
//   d_in[1]: scatter_index int32 or int64 [NTOKENS, TOPK] (device-detected)
//   d_out  : float32 [NTOKENS, HIDDEN]
// ---------------------------------------------------------------------------
extern "C" void kernel_launch(void* const* d_in, const int* in_sizes, int n_in,
                              void* d_out, int out_size) {
    const float* buf = (const float*)d_in[0];
    const void*  idx = d_in[1];
    float*       out = (float*)d_out;

    k_detect<<<1, 1024>>>((const int*)idx);
    k_gather_sum<<<NTOKENS, 256>>>(buf, idx, out);
}

// round 9
// speedup vs baseline: 1.1637x; 1.1589x over previous
#include <cuda_runtime.h>
#include <cstdint>

// Problem constants (from reference)
#define NTOKENS    8192
#define TOPK       2
#define HIDDEN     4096
#define NUM_GROUPS 2
#define M_FULL     (NTOKENS * TOPK)   // 16384
#define NIDX       (NTOKENS * TOPK)   // 16384 index elements

#define CHUNK_F4   32                          // float4 per chunk = 512 B
#define ROW_F4     (HIDDEN / 4)                // 1024 float4 per row
#define NCHUNK     (ROW_F4 / CHUNK_F4)         // 32 chunks
#define TOK_PER_CTA 8                          // 8 warps -> 8 tokens per CTA

// Device scratch (no allocations allowed)
__device__ int g_is64;
__device__ int g_idx32[NIDX];   // indices normalized to int32

// ---------------------------------------------------------------------------
// Pass 0: dtype detection (single block). Views first 16384 int32 words —
// safe for both int32 (64KB, whole buffer) and int64 (128KB, first half).
// int64 -> odd words are high halves of values < 16384 -> all zero.
// ---------------------------------------------------------------------------
__global__ void k_detect(const int* __restrict__ idx32) {
    __shared__ int s_or[32];
    int v = 0;
    #pragma unroll
    for (int r = 0; r < 8; r++)
        v |= idx32[2 * (threadIdx.x + r * 1024) + 1];
    #pragma unroll
    for (int off = 16; off > 0; off >>= 1)
        v |= __shfl_down_sync(0xFFFFFFFFu, v, off);
    if ((threadIdx.x & 31) == 0) s_or[threadIdx.x >> 5] = v;
    __syncthreads();
    if (threadIdx.x < 32) {
        int t = s_or[threadIdx.x];
        #pragma unroll
        for (int off = 16; off > 0; off >>= 1)
            t |= __shfl_down_sync(0xFFFFFFFFu, t, off);
        if (threadIdx.x == 0) g_is64 = (t == 0) ? 1 : 0;
    }
}

// ---------------------------------------------------------------------------
// Pass 1: normalize indices to int32 so the hot kernel is branch-free.
// ---------------------------------------------------------------------------
__global__ void k_prep(const void* __restrict__ idx) {
    int i = blockIdx.x * blockDim.x + threadIdx.x;
    if (i < NIDX) {
        g_idx32[i] = g_is64 ? (int)((const long long*)idx)[i]
                            : ((const int*)idx)[i];
    }
}

// ---------------------------------------------------------------------------
// Pass 2: chunk-major gather-sum.
//   out[t, :] = buf[0,i0,:] + buf[0,i1,:] + buf[1,i0,:] + buf[1,i1,:]
//
//   grid = (NTOKENS/8, NCHUNK), block = 256 (8 warps).
//   Warp w of block (x, c) handles token t = x*8+w, column chunk c.
//   Per chunk, the full source slice (2 groups x 16384 rows x 512B = 16MB,
//   ~10.4MB distinct) is L2-resident, so duplicate-index rows hit L2
//   instead of DRAM. Output stored with __stcs to avoid polluting L2.
// ---------------------------------------------------------------------------
__global__ __launch_bounds__(256) void k_gather_sum(
    const float* __restrict__ buf,
    float*       __restrict__ out)
{
    const int warp = threadIdx.x >> 5;
    const int lane = threadIdx.x & 31;
    const int t    = blockIdx.x * TOK_PER_CTA + warp;
    const int c    = blockIdx.y;

    const int i0 = g_idx32[t * TOPK + 0];
    const int i1 = g_idx32[t * TOPK + 1];

    const float4* __restrict__ b4 = (const float4*)buf;
    const int col = c * CHUNK_F4 + lane;

    const float4 a = __ldg(&b4[(size_t)i0 * ROW_F4 + col]);                       // g0,i0
    const float4 b = __ldg(&b4[(size_t)i1 * ROW_F4 + col]);                       // g0,i1
    const float4 d = __ldg(&b4[((size_t)M_FULL + i0) * ROW_F4 + col]);            // g1,i0
    const float4 e = __ldg(&b4[((size_t)M_FULL + i1) * ROW_F4 + col]);            // g1,i1

    float4 s;
    s.x = (a.x + b.x) + (d.x + e.x);
    s.y = (a.y + b.y) + (d.y + e.y);
    s.z = (a.z + b.z) + (d.z + e.z);
    s.w = (a.w + b.w) + (d.w + e.w);

    __stcs((float4*)out + (size_t)t * ROW_F4 + col, s);
}

// ---------------------------------------------------------------------------
// Launch contract
//   d_in[0]: gemm_buffer   float32 [NUM_GROUPS, M_FULL, HIDDEN]
//   d_in[1]: scatter_index int32 or int64 [NTOKENS, TOPK] (device-detected)
//   d_out  : float32 [NTOKENS, HIDDEN]
// ---------------------------------------------------------------------------
extern "C" void kernel_launch(void* const* d_in, const int* in_sizes, int n_in,
                              void* d_out, int out_size) {
    const float* buf = (const float*)d_in[0];
    const void*  idx = d_in[1];
    float*       out = (float*)d_out;

    k_detect<<<1, 1024>>>((const int*)idx);
    k_prep<<<(NIDX + 255) / 256, 256>>>(idx);

    dim3 grid(NTOKENS / TOK_PER_CTA, NCHUNK);   // (1024, 32)
    k_gather_sum<<<grid, 256>>>(buf, out);
}

// round 10
// speedup vs baseline: 1.1641x; 1.0004x over previous
#include <cuda_runtime.h>
#include <cstdint>

// Problem constants (from reference)
#define NTOKENS    8192
#define TOPK       2
#define HIDDEN     4096
#define NUM_GROUPS 2
#define M_FULL     (NTOKENS * TOPK)   // 16384
#define NIDX       (NTOKENS * TOPK)   // 16384 index elements

#define CHUNK_F4   64                          // float4 per chunk = 1 KB
#define ROW_F4     (HIDDEN / 4)                // 1024 float4 per row
#define NCHUNK     (ROW_F4 / CHUNK_F4)         // 16 chunks
#define TOK_PER_CTA 8                          // 8 warps -> 8 tokens per CTA

// Device scratch (no allocations allowed)
__device__ int g_idx32[NIDX];   // indices normalized to int32

// ---------------------------------------------------------------------------
// Pass 1: normalize indices to int32, with dtype detection fused in.
//   Every block reads the SAME first 32 odd int32 words (128B, L2 broadcast)
//   and computes the flag independently — no cross-block sync needed.
//   int64 -> odd words are high halves of values < 16384 -> all zero.
//   int32 -> odd words are uniform random in [0,16384); P(all 32 == 0) ~ 0.
//   Reading 256B is safe for both dtypes (min buffer = 64KB).
// ---------------------------------------------------------------------------
__global__ __launch_bounds__(256) void k_prep(const void* __restrict__ idx) {
    __shared__ int s_is64;
    if (threadIdx.x < 32) {
        int v = ((const int*)idx)[2 * threadIdx.x + 1];
        #pragma unroll
        for (int off = 16; off > 0; off >>= 1)
            v |= __shfl_down_sync(0xFFFFFFFFu, v, off);
        if (threadIdx.x == 0) s_is64 = (v == 0);
    }
    __syncthreads();
    const bool is64 = (s_is64 != 0);

    int i = blockIdx.x * blockDim.x + threadIdx.x;
    if (i < NIDX) {
        g_idx32[i] = is64 ? (int)((const long long*)idx)[i]
                          : ((const int*)idx)[i];
    }
}

// ---------------------------------------------------------------------------
// Pass 2: chunk-major gather-sum.
//   out[t, :] = buf[0,i0,:] + buf[0,i1,:] + buf[1,i0,:] + buf[1,i1,:]
//
//   grid = (NTOKENS/8, NCHUNK), block = 256 (8 warps).
//   Warp w of block (x, c) handles token t = x*8+w, 1KB column chunk c
//   (each lane: 2 float4 columns, lane and lane+32 -> 8 independent LDG.128).
//   Per chunk, the source slice (2 groups x 16384 rows x 1KB = 32MB,
//   ~21MB distinct) is L2-resident, so duplicate-index rows hit L2 instead
//   of DRAM. Output stored with __stcs (streaming) to not evict the slice.
// ---------------------------------------------------------------------------
__global__ __launch_bounds__(256) void k_gather_sum(
    const float* __restrict__ buf,
    float*       __restrict__ out)
{
    const int warp = threadIdx.x >> 5;
    const int lane = threadIdx.x & 31;
    const int t    = blockIdx.x * TOK_PER_CTA + warp;
    const int c    = blockIdx.y;

    // one broadcast LDG.64 per warp for both indices
    const int2 ii = *(const int2*)&g_idx32[t * TOPK];
    const int i0 = ii.x;
    const int i1 = ii.y;

    const float4* __restrict__ b4 = (const float4*)buf;
    const size_t r00 = (size_t)i0 * ROW_F4;                  // g0, i0
    const size_t r01 = (size_t)i1 * ROW_F4;                  // g0, i1
    const size_t r10 = ((size_t)M_FULL + i0) * ROW_F4;       // g1, i0
    const size_t r11 = ((size_t)M_FULL + i1) * ROW_F4;       // g1, i1

    const int col0 = c * CHUNK_F4 + lane;
    const int col1 = col0 + 32;

    // 8 independent loads in flight
    const float4 a0 = __ldg(&b4[r00 + col0]);
    const float4 b0 = __ldg(&b4[r01 + col0]);
    const float4 d0 = __ldg(&b4[r10 + col0]);
    const float4 e0 = __ldg(&b4[r11 + col0]);
    const float4 a1 = __ldg(&b4[r00 + col1]);
    const float4 b1 = __ldg(&b4[r01 + col1]);
    const float4 d1 = __ldg(&b4[r10 + col1]);
    const float4 e1 = __ldg(&b4[r11 + col1]);

    float4 s0, s1;
    s0.x = (a0.x + b0.x) + (d0.x + e0.x);
    s0.y = (a0.y + b0.y) + (d0.y + e0.y);
    s0.z = (a0.z + b0.z) + (d0.z + e0.z);
    s0.w = (a0.w + b0.w) + (d0.w + e0.w);
    s1.x = (a1.x + b1.x) + (d1.x + e1.x);
    s1.y = (a1.y + b1.y) + (d1.y + e1.y);
    s1.z = (a1.z + b1.z) + (d1.z + e1.z);
    s1.w = (a1.w + b1.w) + (d1.w + e1.w);

    float4* __restrict__ o4 = (float4*)out + (size_t)t * ROW_F4;
    __stcs(&o4[col0], s0);
    __stcs(&o4[col1], s1);
}

// ---------------------------------------------------------------------------
// Launch contract
//   d_in[0]: gemm_buffer   float32 [NUM_GROUPS, M_FULL, HIDDEN]
//   d_in[1]: scatter_index int32 or int64 [NTOKENS, TOPK] (device-detected)
//   d_out  : float32 [NTOKENS, HIDDEN]
// ---------------------------------------------------------------------------
extern "C" void kernel_launch(void* const* d_in, const int* in_sizes, int n_in,
                              void* d_out, int out_size) {
    const float* buf = (const float*)d_in[0];
    const void*  idx = d_in[1];
    float*       out = (float*)d_out;

    k_prep<<<NIDX / 256, 256>>>(idx);

    dim3 grid(NTOKENS / TOK_PER_CTA, NCHUNK);   // (1024, 16)
    k_gather_sum<<<grid, 256>>>(buf, out);
}

// round 11
// speedup vs baseline: 1.1665x; 1.0020x over previous
#include <cuda_runtime.h>
#include <cstdint>

// Problem constants (from reference)
#define NTOKENS    8192
#define TOPK       2
#define HIDDEN     4096
#define NUM_GROUPS 2
#define M_FULL     (NTOKENS * TOPK)   // 16384
#define NIDX       (NTOKENS * TOPK)   // 16384 index elements

#define CHUNK_F4   64                          // float4 per chunk = 1 KB
#define ROW_F4     (HIDDEN / 4)                // 1024 float4 per row
#define NCHUNK     (ROW_F4 / CHUNK_F4)         // 16 chunks
#define TOK_PER_CTA 8                          // 8 warps -> 8 tokens per CTA

// Device scratch (no allocations allowed)
__device__ int g_idx32[NIDX];   // indices normalized to int32

// ---------------------------------------------------------------------------
// Pass 1: normalize indices to int32, with dtype detection fused in.
//   Every block reads the SAME first 32 odd int32 words (128B, L2 broadcast)
//   and computes the flag independently — no cross-block sync needed.
//   int64 -> odd words are high halves of values < 16384 -> all zero.
//   int32 -> odd words are uniform random in [0,16384); P(all 32 == 0) ~ 0.
//   Reading 256B is safe for both dtypes (min buffer = 64KB).
// ---------------------------------------------------------------------------
__global__ __launch_bounds__(256) void k_prep(const void* __restrict__ idx) {
    __shared__ int s_is64;
    if (threadIdx.x < 32) {
        int v = ((const int*)idx)[2 * threadIdx.x + 1];
        #pragma unroll
        for (int off = 16; off > 0; off >>= 1)
            v |= __shfl_down_sync(0xFFFFFFFFu, v, off);
        if (threadIdx.x == 0) s_is64 = (v == 0);
    }
    __syncthreads();
    const bool is64 = (s_is64 != 0);

    int i = blockIdx.x * blockDim.x + threadIdx.x;
    if (i < NIDX) {
        g_idx32[i] = is64 ? (int)((const long long*)idx)[i]
                          : ((const int*)idx)[i];
    }
}

// ---------------------------------------------------------------------------
// Pass 2: chunk-major gather-sum.
//   out[t, :] = buf[0,i0,:] + buf[0,i1,:] + buf[1,i0,:] + buf[1,i1,:]
//
//   grid = (NTOKENS/8, NCHUNK), block = 256 (8 warps).
//   Warp w of block (x, c) handles token t = x*8+w, 1KB column chunk c
//   (each lane: 2 float4 columns, lane and lane+32 -> 8 independent LDG.128).
//   Per chunk, the source slice (2 groups x 16384 rows x 1KB = 32MB,
//   ~21MB distinct) is L2-resident, so duplicate-index rows hit L2 instead
//   of DRAM. Output stored with __stcs (streaming) to not evict the slice.
// ---------------------------------------------------------------------------
__global__ __launch_bounds__(256) void k_gather_sum(
    const float* __restrict__ buf,
    float*       __restrict__ out)
{
    const int warp = threadIdx.x >> 5;
    const int lane = threadIdx.x & 31;
    const int t    = blockIdx.x * TOK_PER_CTA + warp;
    const int c    = blockIdx.y;

    // one broadcast LDG.64 per warp for both indices
    const int2 ii = *(const int2*)&g_idx32[t * TOPK];
    const int i0 = ii.x;
    const int i1 = ii.y;

    const float4* __restrict__ b4 = (const float4*)buf;
    const size_t r00 = (size_t)i0 * ROW_F4;                  // g0, i0
    const size_t r01 = (size_t)i1 * ROW_F4;                  // g0, i1
    const size_t r10 = ((size_t)M_FULL + i0) * ROW_F4;       // g1, i0
    const size_t r11 = ((size_t)M_FULL + i1) * ROW_F4;       // g1, i1

    const int col0 = c * CHUNK_F4 + lane;
    const int col1 = col0 + 32;

    // 8 independent loads in flight
    const float4 a0 = __ldg(&b4[r00 + col0]);
    const float4 b0 = __ldg(&b4[r01 + col0]);
    const float4 d0 = __ldg(&b4[r10 + col0]);
    const float4 e0 = __ldg(&b4[r11 + col0]);
    const float4 a1 = __ldg(&b4[r00 + col1]);
    const float4 b1 = __ldg(&b4[r01 + col1]);
    const float4 d1 = __ldg(&b4[r10 + col1]);
    const float4 e1 = __ldg(&b4[r11 + col1]);

    float4 s0, s1;
    s0.x = (a0.x + b0.x) + (d0.x + e0.x);
    s0.y = (a0.y + b0.y) + (d0.y + e0.y);
    s0.z = (a0.z + b0.z) + (d0.z + e0.z);
    s0.w = (a0.w + b0.w) + (d0.w + e0.w);
    s1.x = (a1.x + b1.x) + (d1.x + e1.x);
    s1.y = (a1.y + b1.y) + (d1.y + e1.y);
    s1.z = (a1.z + b1.z) + (d1.z + e1.z);
    s1.w = (a1.w + b1.w) + (d1.w + e1.w);

    float4* __restrict__ o4 = (float4*)out + (size_t)t * ROW_F4;
    __stcs(&o4[col0], s0);
    __stcs(&o4[col1], s1);
}

// ---------------------------------------------------------------------------
// Launch contract
//   d_in[0]: gemm_buffer   float32 [NUM_GROUPS, M_FULL, HIDDEN]
//   d_in[1]: scatter_index int32 or int64 [NTOKENS, TOPK] (device-detected)
//   d_out  : float32 [NTOKENS, HIDDEN]
// ---------------------------------------------------------------------------
extern "C" void kernel_launch(void* const* d_in, const int* in_sizes, int n_in,
                              void* d_out, int out_size) {
    const float* buf = (const float*)d_in[0];
    const void*  idx = d_in[1];
    float*       out = (float*)d_out;

    k_prep<<<NIDX / 256, 256>>>(idx);

    dim3 grid(NTOKENS / TOK_PER_CTA, NCHUNK);   // (1024, 16)
    k_gather_sum<<<grid, 256>>>(buf, out);
}

// round 12
// speedup vs baseline: 1.2260x; 1.0510x over previous
#include <cuda_runtime.h>
#include <cstdint>

// Problem constants (from reference)
#define NTOKENS    8192
#define TOPK       2
#define HIDDEN     4096
#define NUM_GROUPS 2
#define M_FULL     (NTOKENS * TOPK)   // 16384

#define CHUNK_F4    32                         // float4 per chunk = 512 B
#define ROW_F4      (HIDDEN / 4)               // 1024 float4 per row
#define NCHUNK      (ROW_F4 / CHUNK_F4)        // 32 chunks
#define TOK_PER_CTA 8                          // 8 warps -> 8 tokens per CTA

// ---------------------------------------------------------------------------
// Single fused kernel: out[t,:] = buf[0,i0,:]+buf[0,i1,:]+buf[1,i0,:]+buf[1,i1,:]
//
//   grid = (NTOKENS/8, NCHUNK), block = 256 (8 warps).
//   Warp w of block (x, c) handles token t = x*8+w, 512B column chunk c.
//
//   Index dtype detection is done PER WARP, branch-free of cross-warp sync:
//   all 32 lanes read the same 128B of odd int32 words from the index buffer
//   (L2/L1 broadcast) and OR-reduce with a single REDUX. If the dtype is
//   int64, those words are high halves of values < 16384 -> all zero; if
//   int32 they are uniform random in [0,16384) -> OR nonzero w.p. 1-2^{-448}.
//   Reading 256B is safe for both dtypes (min index buffer = 64KB).
//
//   Chunk-major scheduling: for a fixed chunk c the entire source slice is
//   2 groups x 16384 rows x 512B = 16MB (~10.4MB distinct) -> L2-resident,
//   so duplicate-index rows hit L2 instead of DRAM (read traffic ~324MB
//   instead of 512MB). Output stores use __stcs (streaming) so the 128MB
//   write stream does not evict the slab.
// ---------------------------------------------------------------------------
__global__ __launch_bounds__(256) void k_gather_sum(
    const float* __restrict__ buf,
    const void*  __restrict__ idx,
    float*       __restrict__ out)
{
    const int warp = threadIdx.x >> 5;
    const int lane = threadIdx.x & 31;
    const int t    = blockIdx.x * TOK_PER_CTA + warp;
    const int c    = blockIdx.y;

    // ---- per-warp dtype detection (broadcast read + REDUX) ----
    const int probe = ((const int*)idx)[2 * lane + 1];
    const bool is64 = (__reduce_or_sync(0xFFFFFFFFu, probe) == 0);

    // ---- per-warp index fetch (broadcast load) ----
    int i0, i1;
    if (is64) {
        const longlong2 ll = ((const longlong2*)idx)[t];   // one LDG.128
        i0 = (int)ll.x;
        i1 = (int)ll.y;
    } else {
        const int2 ii = ((const int2*)idx)[t];             // one LDG.64
        i0 = ii.x;
        i1 = ii.y;
    }

    const float4* __restrict__ b4 = (const float4*)buf;
    const int col = c * CHUNK_F4 + lane;

    const size_t r00 = (size_t)i0 * ROW_F4 + col;              // g0, i0
    const size_t r01 = (size_t)i1 * ROW_F4 + col;              // g0, i1
    const size_t r10 = ((size_t)M_FULL + i0) * ROW_F4 + col;   // g1, i0
    const size_t r11 = ((size_t)M_FULL + i1) * ROW_F4 + col;   // g1, i1

    // 4 independent LDG.128 in flight
    const float4 a = __ldg(&b4[r00]);
    const float4 b = __ldg(&b4[r01]);
    const float4 d = __ldg(&b4[r10]);
    const float4 e = __ldg(&b4[r11]);

    float4 s;
    s.x = (a.x + b.x) + (d.x + e.x);
    s.y = (a.y + b.y) + (d.y + e.y);
    s.z = (a.z + b.z) + (d.z + e.z);
    s.w = (a.w + b.w) + (d.w + e.w);

    __stcs((float4*)out + (size_t)t * ROW_F4 + col, s);
}

// ---------------------------------------------------------------------------
// Launch contract
//   d_in[0]: gemm_buffer   float32 [NUM_GROUPS, M_FULL, HIDDEN]
//   d_in[1]: scatter_index int32 or int64 [NTOKENS, TOPK] (device-detected)
//   d_out  : float32 [NTOKENS, HIDDEN]
// ---------------------------------------------------------------------------
extern "C" void kernel_launch(void* const* d_in, const int* in_sizes, int n_in,
                              void* d_out, int out_size) {
    const float* buf = (const float*)d_in[0];
    const void*  idx = d_in[1];
    float*       out = (float*)d_out;

    dim3 grid(NTOKENS / TOK_PER_CTA, NCHUNK);   // (1024, 32)
    k_gather_sum<<<grid, 256>>>(buf, idx, out);
}

// round 13
// speedup vs baseline: 1.2491x; 1.0189x over previous
#include <cuda_runtime.h>
#include <cstdint>

// Problem constants (from reference)
#define NTOKENS    8192
#define TOPK       2
#define HIDDEN     4096
#define NUM_GROUPS 2
#define M_FULL     (NTOKENS * TOPK)   // 16384

#define CHUNK_F4    32                         // float4 per chunk = 512 B
#define ROW_F4      (HIDDEN / 4)               // 1024 float4 per row
#define NCHUNK      (ROW_F4 / CHUNK_F4)        // 32 chunks
#define TOK_PER_CTA 8                          // 8 warps -> 8 tokens per CTA

// ---------------------------------------------------------------------------
// Single fused kernel: out[t,:] = buf[0,i0,:]+buf[0,i1,:]+buf[1,i0,:]+buf[1,i1,:]
//
//   grid = (NTOKENS/8, NCHUNK), block = 256 (8 warps).
//   Warp w of block (x, c) handles token t = x*8+w, 512B column chunk c.
//
//   Index dtype detection is per-warp and BRANCHLESS: the probe load (odd
//   int32 words of the index buffer: all-zero iff dtype is int64, since the
//   values are < 16384), the int64-interpretation load (longlong2) and the
//   int32-interpretation load (int2) are all issued independently, then two
//   SELs pick the right pair once the REDUX resolves. All three are valid
//   reads for either dtype: the int32 buffer is exactly 128KB, and
//   longlong2[t] for t < 8192 spans bytes [16t, 16t+16) <= 128KB.
//   P(int32 misdetected) = 2^-448.
//
//   Chunk-major scheduling: for a fixed chunk c the source slice is
//   2 groups x 16384 rows x 512B = 16MB (~10.4MB distinct) -> L2-resident,
//   so duplicate-index rows hit L2 (read traffic ~324MB, the dedup floor,
//   confirmed by ncu in R12). Output stores use __stcs (streaming) so the
//   128MB write stream does not evict the slab.
// ---------------------------------------------------------------------------
__global__ __launch_bounds__(256) void k_gather_sum(
    const float* __restrict__ buf,
    const void*  __restrict__ idx,
    float*       __restrict__ out)
{
    const int warp = threadIdx.x >> 5;
    const int lane = threadIdx.x & 31;
    const int t    = blockIdx.x * TOK_PER_CTA + warp;
    const int c    = blockIdx.y;

    // --- issue all three index-path loads independently (no branch) ---
    const int       probe = __ldg(&((const int*)idx)[2 * lane + 1]);
    const longlong2 ll    = __ldg(&((const longlong2*)idx)[t]);   // int64 view
    const int2      ii    = __ldg(&((const int2*)idx)[t]);        // int32 view

    const bool is64 = (__reduce_or_sync(0xFFFFFFFFu, probe) == 0);
    const int i0 = is64 ? (int)ll.x : ii.x;
    const int i1 = is64 ? (int)ll.y : ii.y;

    const float4* __restrict__ b4 = (const float4*)buf;
    const int col = c * CHUNK_F4 + lane;

    const size_t r00 = (size_t)i0 * ROW_F4 + col;              // g0, i0
    const size_t r01 = (size_t)i1 * ROW_F4 + col;              // g0, i1
    const size_t r10 = ((size_t)M_FULL + i0) * ROW_F4 + col;   // g1, i0
    const size_t r11 = ((size_t)M_FULL + i1) * ROW_F4 + col;   // g1, i1

    // 4 independent LDG.128 in flight
    const float4 a = __ldg(&b4[r00]);
    const float4 b = __ldg(&b4[r01]);
    const float4 d = __ldg(&b4[r10]);
    const float4 e = __ldg(&b4[r11]);

    float4 s;
    s.x = (a.x + b.x) + (d.x + e.x);
    s.y = (a.y + b.y) + (d.y + e.y);
    s.z = (a.z + b.z) + (d.z + e.z);
    s.w = (a.w + b.w) + (d.w + e.w);

    __stcs((float4*)out + (size_t)t * ROW_F4 + col, s);
}

// ---------------------------------------------------------------------------
// Launch contract
//   d_in[0]: gemm_buffer   float32 [NUM_GROUPS, M_FULL, HIDDEN]
//   d_in[1]: scatter_index int32 or int64 [NTOKENS, TOPK] (device-detected)
//   d_out  : float32 [NTOKENS, HIDDEN]
// ---------------------------------------------------------------------------
extern "C" void kernel_launch(void* const* d_in, const int* in_sizes, int n_in,
                              void* d_out, int out_size) {
    const float* buf = (const float*)d_in[0];
    const void*  idx = d_in[1];
    float*       out = (float*)d_out;

    dim3 grid(NTOKENS / TOK_PER_CTA, NCHUNK);   // (1024, 32)
    k_gather_sum<<<grid, 256>>>(buf, idx, out);
}